// round 5
// baseline (speedup 1.0000x reference)
#include <cuda_runtime.h>
#include <cstdint>

// Problem constants (fixed by setup_inputs: N=64, T=400, D=1024, M=256)
#define NTOK 25600
#define DDIM 1024
#define MCOD 256
#define ROWS_PER_BLK 64
#define KC 16
#define XLD 68  // padded row stride for xs tile (bank-conflict mitigation)

typedef unsigned long long u64;

// ---------------- packed fp32x2 helpers (sm_100+ PTX, not "a"-gated) ----------------
static __device__ __forceinline__ u64 ffma2(u64 a, u64 b, u64 c) {
    u64 d;
    asm("fma.rn.f32x2 %0, %1, %2, %3;" : "=l"(d) : "l"(a), "l"(b), "l"(c));
    return d;
}
static __device__ __forceinline__ u64 pack2(float lo, float hi) {
    u64 d;
    asm("mov.b64 %0, {%1, %2};" : "=l"(d) : "f"(lo), "f"(hi));
    return d;
}
static __device__ __forceinline__ float2 unpack2(u64 v) {
    float lo, hi;
    asm("mov.b64 {%0, %1}, %2;" : "=f"(lo), "=f"(hi) : "l"(v));
    return make_float2(lo, hi);
}

// ---------------- device scratch (allocation-free per harness rules) ----------------
__device__ float  g_enorm[MCOD * DDIM];
__device__ float  g_se[MCOD];
__device__ int    g_counts[MCOD];
__device__ double g_loss;

// ---------------------------------------------------------------------------
// Zero accumulators (must run every launch: graph replays reuse globals)
// ---------------------------------------------------------------------------
__global__ void vq_init() {
    int t = threadIdx.x;
    g_counts[t] = 0;
    if (t == 0) g_loss = 0.0;
}

// ---------------------------------------------------------------------------
// emb_norm[m] = emb[m] / (||emb[m]|| + 1e-4);  se[m] = sum(emb_norm[m]^2)
// Replicates reference rounding: fp32 sum -> sqrtf (IEEE) -> +1e-4 -> IEEE div
// ---------------------------------------------------------------------------
__global__ __launch_bounds__(256) void vq_normalize(const float* __restrict__ emb) {
    __shared__ float red[256];
    const int m = blockIdx.x;
    const int t = threadIdx.x;

    float4 v = ((const float4*)(emb + (size_t)m * DDIM))[t];
    float p = v.x * v.x + v.y * v.y + v.z * v.z + v.w * v.w;
    red[t] = p;
    __syncthreads();
    for (int s = 128; s > 0; s >>= 1) {
        if (t < s) red[t] += red[t + s];
        __syncthreads();
    }
    float denom = __fadd_rn(sqrtf(red[0]), 1e-4f);
    __syncthreads();

    float4 e;
    e.x = __fdiv_rn(v.x, denom);
    e.y = __fdiv_rn(v.y, denom);
    e.z = __fdiv_rn(v.z, denom);
    e.w = __fdiv_rn(v.w, denom);
    ((float4*)(g_enorm + (size_t)m * DDIM))[t] = e;

    float p2 = e.x * e.x + e.y * e.y + e.z * e.z + e.w * e.w;
    red[t] = p2;
    __syncthreads();
    for (int s = 128; s > 0; s >>= 1) {
        if (t < s) red[t] += red[t + s];
        __syncthreads();
    }
    if (t == 0) g_se[m] = red[0];
}

// ---------------------------------------------------------------------------
// Fused: distances GEMM (64 rows x 256 codes per block) on the PACKED f32x2
// FMA pipe + argmin (reference fp32 rounding + lowest-index tiebreak) +
// gather + ST output + commitment loss partial + code counts.
// Thread layout: 256 threads = 16 ty (row groups of 4) x 16 tx2 (code groups
// of 16).  acc2[4 rows][8 code-pairs] packed register microkernel.
// Per-lane fma.rn.f32x2 == scalar __fmaf_rn in the same k-order, so the
// distances (and hence the argmin + output) are bitwise identical to the
// scalar round-3 kernel.
// ---------------------------------------------------------------------------
__global__ __launch_bounds__(256) void vq_main(const float* __restrict__ x,
                                               const float* __restrict__ emb,
                                               float* __restrict__ out) {
    __shared__ __align__(16) float xs[KC][XLD];
    __shared__ __align__(16) float es[KC][MCOD];
    __shared__ int   sidx[ROWS_PER_BLK];
    __shared__ float sred[256];

    const int t   = threadIdx.x;
    const int ty  = t >> 4;
    const int tx2 = t & 15;
    const size_t rowBase = (size_t)blockIdx.x * ROWS_PER_BLK;

    u64 acc2[4][8];
#pragma unroll
    for (int i = 0; i < 4; i++)
#pragma unroll
        for (int j = 0; j < 8; j++) acc2[i][j] = 0ull;
    u64 sx2[2] = {0ull, 0ull};

    // Tile-load mapping: x tile -> each thread one float4 (row lr, quad lq);
    // e tile -> thread t owns code row t (16 contiguous floats per chunk).
    const int lr = t >> 2;
    const int lq = t & 3;
    const float* xld = x + (rowBase + lr) * DDIM + lq * 4;
    const float* eld = g_enorm + (size_t)t * DDIM;

    for (int k0 = 0; k0 < DDIM; k0 += KC) {
        float4 xv = *(const float4*)(xld + k0);
        xs[lq * 4 + 0][lr] = xv.x;
        xs[lq * 4 + 1][lr] = xv.y;
        xs[lq * 4 + 2][lr] = xv.z;
        xs[lq * 4 + 3][lr] = xv.w;
#pragma unroll
        for (int q = 0; q < 4; q++) {
            float4 ev = *(const float4*)(eld + k0 + q * 4);
            es[q * 4 + 0][t] = ev.x;
            es[q * 4 + 1][t] = ev.y;
            es[q * 4 + 2][t] = ev.z;
            es[q * 4 + 3][t] = ev.w;
        }
        __syncthreads();

#pragma unroll
        for (int k = 0; k < KC; k++) {
            float4 xr4 = *(const float4*)&xs[k][ty * 4];
            // sum(x^2) packed: {x0,x1}^2 and {x2,x3}^2
            u64 xp01 = pack2(xr4.x, xr4.y);
            u64 xp23 = pack2(xr4.z, xr4.w);
            sx2[0] = ffma2(xp01, xp01, sx2[0]);
            sx2[1] = ffma2(xp23, xp23, sx2[1]);
            // broadcast-duplicated row values
            u64 xd[4];
            xd[0] = pack2(xr4.x, xr4.x);
            xd[1] = pack2(xr4.y, xr4.y);
            xd[2] = pack2(xr4.z, xr4.z);
            xd[3] = pack2(xr4.w, xr4.w);
#pragma unroll
            for (int g = 0; g < 4; g++) {
                // float4 {e0,e1,e2,e3} reinterpreted as packed pairs {e0,e1},{e2,e3}
                ulonglong2 ep = *(const ulonglong2*)&es[k][g * 64 + tx2 * 4];
#pragma unroll
                for (int i = 0; i < 4; i++) {
                    acc2[i][g * 2 + 0] = ffma2(xd[i], ep.x, acc2[i][g * 2 + 0]);
                    acc2[i][g * 2 + 1] = ffma2(xd[i], ep.y, acc2[i][g * 2 + 1]);
                }
            }
        }
        __syncthreads();
    }

    // unpack per-row sum(x^2)
    float2 s01 = unpack2(sx2[0]);
    float2 s23 = unpack2(sx2[1]);
    float sx[4] = {s01.x, s01.y, s23.x, s23.y};

    // Per-thread argmin over its 16 codes using reference rounding:
    //   d = fl( fl(se + sx) - fl(2*dot) ), lowest index wins ties.
    float bestD[4] = {3.4e38f, 3.4e38f, 3.4e38f, 3.4e38f};
    int   bestI[4] = {0, 0, 0, 0};
#pragma unroll
    for (int g = 0; g < 4; g++) {
#pragma unroll
        for (int p = 0; p < 2; p++) {
#pragma unroll
            for (int i = 0; i < 4; i++) {
                float2 dot2 = unpack2(acc2[i][g * 2 + p]);
                const int c0 = g * 64 + tx2 * 4 + 2 * p;
                float d0 = __fsub_rn(__fadd_rn(g_se[c0], sx[i]),
                                     __fmul_rn(2.0f, dot2.x));
                if (d0 < bestD[i] || (d0 == bestD[i] && c0 < bestI[i])) {
                    bestD[i] = d0;
                    bestI[i] = c0;
                }
                float d1 = __fsub_rn(__fadd_rn(g_se[c0 + 1], sx[i]),
                                     __fmul_rn(2.0f, dot2.y));
                if (d1 < bestD[i] || (d1 == bestD[i] && (c0 + 1) < bestI[i])) {
                    bestD[i] = d1;
                    bestI[i] = c0 + 1;
                }
            }
        }
    }

    // Reduce across the 16 tx2 lanes (contiguous half-warp segments).
#pragma unroll
    for (int i = 0; i < 4; i++) {
        float d = bestD[i];
        int   bi = bestI[i];
        for (int off = 8; off > 0; off >>= 1) {
            float od = __shfl_down_sync(0xffffffffu, d, off, 16);
            int   oi = __shfl_down_sync(0xffffffffu, bi, off, 16);
            if (od < d || (od == d && oi < bi)) { d = od; bi = oi; }
        }
        if (tx2 == 0) sidx[ty * 4 + i] = bi;
    }
    __syncthreads();

    if (t < ROWS_PER_BLK) atomicAdd(&g_counts[sidx[t]], 1);

    // Gather + straight-through output + loss.
    // quantized_ = fl( fl( fl(x + fl(q-x)) + q ) * 0.5 )  (exactly as reference)
    float lloss = 0.f;
    for (int r = 0; r < ROWS_PER_BLK; ++r) {
        const int idx = sidx[r];
        float4 q  = ((const float4*)(emb + (size_t)idx * DDIM))[t];
        float4 xv = ((const float4*)(x + (rowBase + r) * DDIM))[t];
        float4 o;
        {
            float st = __fadd_rn(xv.x, __fsub_rn(q.x, xv.x));
            o.x = __fmul_rn(__fadd_rn(st, q.x), 0.5f);
            float dd = __fsub_rn(xv.x, q.x);
            lloss = __fmaf_rn(dd, dd, lloss);
        }
        {
            float st = __fadd_rn(xv.y, __fsub_rn(q.y, xv.y));
            o.y = __fmul_rn(__fadd_rn(st, q.y), 0.5f);
            float dd = __fsub_rn(xv.y, q.y);
            lloss = __fmaf_rn(dd, dd, lloss);
        }
        {
            float st = __fadd_rn(xv.z, __fsub_rn(q.z, xv.z));
            o.z = __fmul_rn(__fadd_rn(st, q.z), 0.5f);
            float dd = __fsub_rn(xv.z, q.z);
            lloss = __fmaf_rn(dd, dd, lloss);
        }
        {
            float st = __fadd_rn(xv.w, __fsub_rn(q.w, xv.w));
            o.w = __fmul_rn(__fadd_rn(st, q.w), 0.5f);
            float dd = __fsub_rn(xv.w, q.w);
            lloss = __fmaf_rn(dd, dd, lloss);
        }
        ((float4*)out)[(rowBase + r) * (DDIM / 4) + t] = o;
    }

    sred[t] = lloss;
    __syncthreads();
    for (int s = 128; s > 0; s >>= 1) {
        if (t < s) sred[t] += sred[t + s];
        __syncthreads();
    }
    if (t == 0) atomicAdd(&g_loss, (double)sred[0]);
}

// ---------------------------------------------------------------------------
// Scalars: commitment_loss = mean((x-q)^2), perplexity = exp(-sum p log(p+1e-10))
// ---------------------------------------------------------------------------
__global__ void vq_finalize(float* __restrict__ out) {
    __shared__ float red[256];
    const int t = threadIdx.x;
    float p = (float)g_counts[t] / 25600.0f;
    float term = __fmul_rn(p, logf(__fadd_rn(p, 1e-10f)));
    red[t] = term;
    __syncthreads();
    for (int s = 128; s > 0; s >>= 1) {
        if (t < s) red[t] += red[t + s];
        __syncthreads();
    }
    if (t == 0) {
        out[26214400] = (float)(g_loss / 26214400.0);
        out[26214401] = expf(-red[0]);
    }
}

extern "C" void kernel_launch(void* const* d_in, const int* in_sizes, int n_in,
                              void* d_out, int out_size) {
    const float* x   = (const float*)d_in[0];
    const float* emb = (const float*)d_in[1];
    float* out = (float*)d_out;

    vq_init<<<1, 256>>>();
    vq_normalize<<<MCOD, 256>>>(emb);
    vq_main<<<NTOK / ROWS_PER_BLK, 256>>>(x, emb, out);
    vq_finalize<<<1, 256>>>(out);
}

// round 6
// speedup vs baseline: 1.0397x; 1.0397x over previous
#include <cuda_runtime.h>
#include <cstdint>

// Problem constants (fixed by setup_inputs: N=64, T=400, D=1024, M=256)
#define NTOK 25600
#define DDIM 1024
#define MCOD 256
#define ROWS_PER_BLK 64
#define KC 16

typedef unsigned long long u64;

// ---------------- packed fp32x2 helpers (sm_100+ PTX, not "a"-gated) ----------------
static __device__ __forceinline__ u64 ffma2(u64 a, u64 b, u64 c) {
    u64 d;
    asm("fma.rn.f32x2 %0, %1, %2, %3;" : "=l"(d) : "l"(a), "l"(b), "l"(c));
    return d;
}
static __device__ __forceinline__ u64 pack2(float lo, float hi) {
    u64 d;
    asm("mov.b64 %0, {%1, %2};" : "=l"(d) : "f"(lo), "f"(hi));
    return d;
}
static __device__ __forceinline__ float2 unpack2(u64 v) {
    float lo, hi;
    asm("mov.b64 {%0, %1}, %2;" : "=f"(lo), "=f"(hi) : "l"(v));
    return make_float2(lo, hi);
}

// ---------------- device scratch (allocation-free per harness rules) ----------------
__device__ float  g_enorm[MCOD * DDIM];
__device__ float  g_se[MCOD];
__device__ int    g_counts[MCOD];
__device__ double g_loss;

// ---------------------------------------------------------------------------
// Zero accumulators (must run every launch: graph replays reuse globals)
// ---------------------------------------------------------------------------
__global__ void vq_init() {
    int t = threadIdx.x;
    g_counts[t] = 0;
    if (t == 0) g_loss = 0.0;
}

// ---------------------------------------------------------------------------
// emb_norm[m] = emb[m] / (||emb[m]|| + 1e-4);  se[m] = sum(emb_norm[m]^2)
// Replicates reference rounding: fp32 sum -> sqrtf (IEEE) -> +1e-4 -> IEEE div
// ---------------------------------------------------------------------------
__global__ __launch_bounds__(256) void vq_normalize(const float* __restrict__ emb) {
    __shared__ float red[256];
    const int m = blockIdx.x;
    const int t = threadIdx.x;

    float4 v = ((const float4*)(emb + (size_t)m * DDIM))[t];
    float p = v.x * v.x + v.y * v.y + v.z * v.z + v.w * v.w;
    red[t] = p;
    __syncthreads();
    for (int s = 128; s > 0; s >>= 1) {
        if (t < s) red[t] += red[t + s];
        __syncthreads();
    }
    float denom = __fadd_rn(sqrtf(red[0]), 1e-4f);
    __syncthreads();

    float4 e;
    e.x = __fdiv_rn(v.x, denom);
    e.y = __fdiv_rn(v.y, denom);
    e.z = __fdiv_rn(v.z, denom);
    e.w = __fdiv_rn(v.w, denom);
    ((float4*)(g_enorm + (size_t)m * DDIM))[t] = e;

    float p2 = e.x * e.x + e.y * e.y + e.z * e.z + e.w * e.w;
    red[t] = p2;
    __syncthreads();
    for (int s = 128; s > 0; s >>= 1) {
        if (t < s) red[t] += red[t + s];
        __syncthreads();
    }
    if (t == 0) g_se[m] = red[0];
}

// ---------------------------------------------------------------------------
// Fused: distances GEMM (64 rows x 256 codes per block) on the packed f32x2
// FMA pipe with ZERO in-loop packing: x tile stored pre-duplicated as u64
// pairs in smem, e tile pairs read directly as ulonglong2.  sum(x^2) moved
// out of the inner loop (accumulated at tile-load, butterfly-reduced).
// Thread layout: 256 threads = 16 ty (rows of 4) x 16 tx2 (codes of 16).
// acc2[4 rows][8 code-pairs].  Per-lane fma.rn.f32x2 rounds identically to
// scalar __fmaf_rn in the same k-order -> distances/argmin/output bitwise
// identical to the round-3 kernel.
// ---------------------------------------------------------------------------
__global__ __launch_bounds__(256) void vq_main(const float* __restrict__ x,
                                               const float* __restrict__ emb,
                                               float* __restrict__ out) {
    __shared__ __align__(16) u64   xsd[KC][ROWS_PER_BLK];   // duplicated x pairs (8KB)
    __shared__ __align__(16) float es[KC][MCOD];            // e tile (16KB)
    __shared__ float ssx[ROWS_PER_BLK];
    __shared__ int   sidx[ROWS_PER_BLK];
    __shared__ float sred[256];

    const int t   = threadIdx.x;
    const int ty  = t >> 4;
    const int tx2 = t & 15;
    const size_t rowBase = (size_t)blockIdx.x * ROWS_PER_BLK;

    u64 acc2[4][8];
#pragma unroll
    for (int i = 0; i < 4; i++)
#pragma unroll
        for (int j = 0; j < 8; j++) acc2[i][j] = 0ull;

    // Tile-load mapping: x tile -> each thread one float4 (row lr, quad lq);
    // e tile -> thread t owns code row t (16 contiguous floats per chunk).
    const int lr = t >> 2;
    const int lq = t & 3;
    const float* xld = x + (rowBase + lr) * DDIM + lq * 4;
    const float* eld = g_enorm + (size_t)t * DDIM;
    float sxp = 0.f;   // partial sum(x^2) for row lr (this thread's quads)

    for (int k0 = 0; k0 < DDIM; k0 += KC) {
        float4 xv = *(const float4*)(xld + k0);
        sxp = __fmaf_rn(xv.x, xv.x, sxp);
        sxp = __fmaf_rn(xv.y, xv.y, sxp);
        sxp = __fmaf_rn(xv.z, xv.z, sxp);
        sxp = __fmaf_rn(xv.w, xv.w, sxp);
        xsd[lq * 4 + 0][lr] = pack2(xv.x, xv.x);
        xsd[lq * 4 + 1][lr] = pack2(xv.y, xv.y);
        xsd[lq * 4 + 2][lr] = pack2(xv.z, xv.z);
        xsd[lq * 4 + 3][lr] = pack2(xv.w, xv.w);
#pragma unroll
        for (int q = 0; q < 4; q++) {
            float4 ev = *(const float4*)(eld + k0 + q * 4);
            es[q * 4 + 0][t] = ev.x;
            es[q * 4 + 1][t] = ev.y;
            es[q * 4 + 2][t] = ev.z;
            es[q * 4 + 3][t] = ev.w;
        }
        __syncthreads();

#pragma unroll
        for (int k = 0; k < KC; k++) {
            ulonglong2 xa = *(const ulonglong2*)&xsd[k][ty * 4];       // rows 0,1
            ulonglong2 xb = *(const ulonglong2*)&xsd[k][ty * 4 + 2];   // rows 2,3
            u64 xd[4] = {xa.x, xa.y, xb.x, xb.y};
#pragma unroll
            for (int g = 0; g < 4; g++) {
                // float4 {e0,e1,e2,e3} reinterpreted as packed pairs {e0,e1},{e2,e3}
                ulonglong2 ep = *(const ulonglong2*)&es[k][g * 64 + tx2 * 4];
#pragma unroll
                for (int i = 0; i < 4; i++) {
                    acc2[i][g * 2 + 0] = ffma2(xd[i], ep.x, acc2[i][g * 2 + 0]);
                    acc2[i][g * 2 + 1] = ffma2(xd[i], ep.y, acc2[i][g * 2 + 1]);
                }
            }
        }
        __syncthreads();
    }

    // Combine the 4 quad-partials of sum(x^2) for row lr (lanes t&~3 .. t|3).
    sxp += __shfl_xor_sync(0xffffffffu, sxp, 1);
    sxp += __shfl_xor_sync(0xffffffffu, sxp, 2);
    if (lq == 0) ssx[lr] = sxp;
    __syncthreads();

    const float sx[4] = {ssx[ty * 4 + 0], ssx[ty * 4 + 1],
                         ssx[ty * 4 + 2], ssx[ty * 4 + 3]};

    // Per-thread argmin over its 16 codes using reference rounding:
    //   d = fl( fl(se + sx) - fl(2*dot) ), lowest index wins ties.
    float bestD[4] = {3.4e38f, 3.4e38f, 3.4e38f, 3.4e38f};
    int   bestI[4] = {0, 0, 0, 0};
#pragma unroll
    for (int g = 0; g < 4; g++) {
#pragma unroll
        for (int p = 0; p < 2; p++) {
            const int c0 = g * 64 + tx2 * 4 + 2 * p;
            const float se0 = g_se[c0], se1 = g_se[c0 + 1];
#pragma unroll
            for (int i = 0; i < 4; i++) {
                float2 dot2 = unpack2(acc2[i][g * 2 + p]);
                float d0 = __fsub_rn(__fadd_rn(se0, sx[i]), __fmul_rn(2.0f, dot2.x));
                if (d0 < bestD[i] || (d0 == bestD[i] && c0 < bestI[i])) {
                    bestD[i] = d0;
                    bestI[i] = c0;
                }
                float d1 = __fsub_rn(__fadd_rn(se1, sx[i]), __fmul_rn(2.0f, dot2.y));
                if (d1 < bestD[i] || (d1 == bestD[i] && (c0 + 1) < bestI[i])) {
                    bestD[i] = d1;
                    bestI[i] = c0 + 1;
                }
            }
        }
    }

    // Reduce across the 16 tx2 lanes (contiguous half-warp segments).
#pragma unroll
    for (int i = 0; i < 4; i++) {
        float d = bestD[i];
        int   bi = bestI[i];
        for (int off = 8; off > 0; off >>= 1) {
            float od = __shfl_down_sync(0xffffffffu, d, off, 16);
            int   oi = __shfl_down_sync(0xffffffffu, bi, off, 16);
            if (od < d || (od == d && oi < bi)) { d = od; bi = oi; }
        }
        if (tx2 == 0) sidx[ty * 4 + i] = bi;
    }
    __syncthreads();

    if (t < ROWS_PER_BLK) atomicAdd(&g_counts[sidx[t]], 1);

    // Gather + straight-through output + loss.
    // quantized_ = fl( fl( fl(x + fl(q-x)) + q ) * 0.5 )  (exactly as reference)
    float lloss = 0.f;
    for (int r = 0; r < ROWS_PER_BLK; ++r) {
        const int idx = sidx[r];
        float4 q  = ((const float4*)(emb + (size_t)idx * DDIM))[t];
        float4 xv = ((const float4*)(x + (rowBase + r) * DDIM))[t];
        float4 o;
        {
            float st = __fadd_rn(xv.x, __fsub_rn(q.x, xv.x));
            o.x = __fmul_rn(__fadd_rn(st, q.x), 0.5f);
            float dd = __fsub_rn(xv.x, q.x);
            lloss = __fmaf_rn(dd, dd, lloss);
        }
        {
            float st = __fadd_rn(xv.y, __fsub_rn(q.y, xv.y));
            o.y = __fmul_rn(__fadd_rn(st, q.y), 0.5f);
            float dd = __fsub_rn(xv.y, q.y);
            lloss = __fmaf_rn(dd, dd, lloss);
        }
        {
            float st = __fadd_rn(xv.z, __fsub_rn(q.z, xv.z));
            o.z = __fmul_rn(__fadd_rn(st, q.z), 0.5f);
            float dd = __fsub_rn(xv.z, q.z);
            lloss = __fmaf_rn(dd, dd, lloss);
        }
        {
            float st = __fadd_rn(xv.w, __fsub_rn(q.w, xv.w));
            o.w = __fmul_rn(__fadd_rn(st, q.w), 0.5f);
            float dd = __fsub_rn(xv.w, q.w);
            lloss = __fmaf_rn(dd, dd, lloss);
        }
        ((float4*)out)[(rowBase + r) * (DDIM / 4) + t] = o;
    }

    sred[t] = lloss;
    __syncthreads();
    for (int s = 128; s > 0; s >>= 1) {
        if (t < s) sred[t] += sred[t + s];
        __syncthreads();
    }
    if (t == 0) atomicAdd(&g_loss, (double)sred[0]);
}

// ---------------------------------------------------------------------------
// Scalars: commitment_loss = mean((x-q)^2), perplexity = exp(-sum p log(p+1e-10))
// ---------------------------------------------------------------------------
__global__ void vq_finalize(float* __restrict__ out) {
    __shared__ float red[256];
    const int t = threadIdx.x;
    float p = (float)g_counts[t] / 25600.0f;
    float term = __fmul_rn(p, logf(__fadd_rn(p, 1e-10f)));
    red[t] = term;
    __syncthreads();
    for (int s = 128; s > 0; s >>= 1) {
        if (t < s) red[t] += red[t + s];
        __syncthreads();
    }
    if (t == 0) {
        out[26214400] = (float)(g_loss / 26214400.0);
        out[26214401] = expf(-red[0]);
    }
}

extern "C" void kernel_launch(void* const* d_in, const int* in_sizes, int n_in,
                              void* d_out, int out_size) {
    const float* x   = (const float*)d_in[0];
    const float* emb = (const float*)d_in[1];
    float* out = (float*)d_out;

    vq_init<<<1, 256>>>();
    vq_normalize<<<MCOD, 256>>>(emb);
    vq_main<<<NTOK / ROWS_PER_BLK, 256>>>(x, emb, out);
    vq_finalize<<<1, 256>>>(out);
}